// round 8
// baseline (speedup 1.0000x reference)
#include <cuda_runtime.h>
#include <cstdint>

#define B_    256
#define DIN   700
#define T_    250
#define H_    1024
#define DOUT  20
#define NW    8        // 32-bit words covering T_=250 bits
#define DINP  704      // padded DIN
#define MAXL  256      // max active inputs per (b,t) list (multiple of 8)
#define NROW  (B_*T_)  // 64000
#define HS    64       // h columns per phase-A block slice
#define NBG   9        // b-groups in phase A
#define BPB   29       // b per group (9*29=261 >= 256)
#define ZROW  DIN      // dummy zero W row index (row 700)

#define PACK_BLK ((B_*DIN + 7) / 8)                 // 22400
#define TR_TOT   ((DIN+1)*H_ + H_*DOUT)             // 738304
#define TR_BLK   ((TR_TOT + 255) / 256)             // 2884
#define SOP      22                                  // padded sO row stride (floats)

// ---------------- scratch (static device memory; no allocations) -------------
__device__ float          g_Wt[(DIN+1)*H_];                 // W_hid^T [i][h], row 700 = zeros
__device__ float          g_WoT[H_*DOUT];                   // W_out^T  [h][o]
__device__ unsigned       g_words[B_*NW*DINP];              // spike bits [(b*8+w)*704 + i], bit = t%32
__device__ unsigned short g_lists[(size_t)NROW*MAXL];       // active input indices per (b,t), pair-padded
__device__ int            g_counts[NROW];                   // pair-max counts (multiple of 8)
__device__ float          g_I[(size_t)NROW*H_];             // hidden input currents [b][t][h]

// ---------------- K0: fused pack (spikes->bits) + transposes ------------------
__global__ void k_prep(const float* __restrict__ sd, const float* __restrict__ Wh,
                       const float* __restrict__ Wo) {
    if (blockIdx.x < PACK_BLK) {
        int gw   = blockIdx.x * 8 + (threadIdx.x >> 5);
        int lane = threadIdx.x & 31;
        if (gw >= B_ * DIN) return;
        int b = gw / DIN, i = gw % DIN;
        const float* p = sd + ((size_t)b * DIN + i) * T_;
#pragma unroll
        for (int w = 0; w < NW; w++) {
            int t = w * 32 + lane;
            float v = (t < T_) ? p[t] : 0.0f;
            unsigned m = __ballot_sync(0xffffffffu, v > 0.5f);
            if (lane == 0) g_words[(b * NW + w) * DINP + i] = m;
        }
    } else {
        int e = (blockIdx.x - PACK_BLK) * 256 + threadIdx.x;
        if (e >= TR_TOT) return;
        if (e < (DIN + 1) * H_) {
            int i = e / H_, h = e % H_;
            g_Wt[e] = (i < DIN) ? Wh[h * DIN + i] : 0.0f;
        } else {
            int e2 = e - (DIN + 1) * H_;
            int h = e2 / DOUT, o = e2 % DOUT;
            g_WoT[e2] = Wo[o * H_ + h];
        }
    }
}

// ---------------- K2a: active-index lists, pair-padded -------------------------
__global__ void k_lists() {
    __shared__ unsigned sw[DINP];
    __shared__ int scnt[32];
    int b = blockIdx.x / NW, w = blockIdx.x % NW;
    for (int i = threadIdx.x; i < DIN; i += blockDim.x)
        sw[i] = g_words[(b * NW + w) * DINP + i];
    __syncthreads();
    int wi = threadIdx.x >> 5, lane = threadIdx.x & 31;
    for (int tt = wi; tt < 32; tt += 8) {
        int t = w * 32 + tt;
        if (t >= T_) { if (lane == 0) scnt[tt] = 0; continue; }
        int row = b * T_ + t;
        unsigned short* lst = &g_lists[(size_t)row * MAXL];
        int cnt = 0;
        for (int base = 0; base < DINP; base += 32) {
            int i = base + lane;
            unsigned hit = (i < DIN) ? ((sw[i] >> tt) & 1u) : 0u;
            unsigned m = __ballot_sync(0xffffffffu, hit != 0u);
            if (hit) {
                int pos = cnt + __popc(m & ((1u << lane) - 1u));
                if (pos < MAXL) lst[pos] = (unsigned short)i;
            }
            cnt += __popc(m);
        }
        cnt = min(cnt, MAXL);
        int cnt_pad = (cnt + 7) & ~7;
        if (cnt + lane < cnt_pad) lst[cnt + lane] = (unsigned short)ZROW;
        if (lane == 0) scnt[tt] = cnt_pad;
    }
    __syncthreads();
    for (int tt = wi; tt < 32; tt += 8) {
        int t = w * 32 + tt;
        if (t >= T_) continue;
        int row = b * T_ + t;
        int mine = scnt[tt];
        int pm = max(mine, scnt[tt ^ 1]);          // pair partner
        unsigned short* lst = &g_lists[(size_t)row * MAXL];
        for (int e = mine + lane; e < pm; e += 32) lst[e] = (unsigned short)ZROW;
        if (lane == 0) g_counts[row] = pm;
    }
}

// ---------------- K2b: sparse hidden GEMM (I = xs @ W_hid^T) -------------------
// Warp = row pair; half-warp per row; f32x2 adds; prefetched index LDG.128.
__global__ __launch_bounds__(1024, 1) void k_phaseA() {
    extern __shared__ float sW[];                // [(DIN+1)][HS]
    int hsIdx = blockIdx.x / NBG;
    int bg    = blockIdx.x % NBG;
    int h0    = hsIdx * HS;

    for (int e = threadIdx.x; e < (DIN + 1) * (HS / 4); e += blockDim.x) {
        int i = e >> 4, c = e & 15;
        ((float4*)sW)[e] = *(const float4*)&g_Wt[i * H_ + h0 + c * 4];
    }
    __syncthreads();

    int warpId = threadIdx.x >> 5, lane = threadIdx.x & 31;
    int half = lane >> 4, hl = lane & 15;
    const char* sWb = (const char*)sW + hl * 16;

    int bstart = bg * BPB;
    int nb = min(BPB, B_ - bstart);
    int npr = nb * (T_ / 2);

    for (int p = warpId; p < npr; p += 32) {
        int b  = bstart + p / (T_ / 2);
        int tp = (p % (T_ / 2)) * 2;
        int row = b * T_ + tp + half;
        int cnt = g_counts[row];
        const unsigned short* lst = &g_lists[(size_t)row * MAXL];
        unsigned long long a0 = 0ull, a1 = 0ull;
        uint4 pk = *(const uint4*)lst;
        for (int base = 0; base < cnt; base += 8) {
            uint4 cur = pk;
            if (base + 8 < cnt) pk = *(const uint4*)(lst + base + 8);
            unsigned j; ulonglong2 wv;
#define STEP(JE) \
            j = (JE); \
            wv = *(const ulonglong2*)(sWb + j * 256u); \
            asm("add.rn.f32x2 %0, %0, %1;" : "+l"(a0) : "l"(wv.x)); \
            asm("add.rn.f32x2 %0, %0, %1;" : "+l"(a1) : "l"(wv.y));
            STEP(cur.x & 0xFFFFu) STEP(cur.x >> 16)
            STEP(cur.y & 0xFFFFu) STEP(cur.y >> 16)
            STEP(cur.z & 0xFFFFu) STEP(cur.z >> 16)
            STEP(cur.w & 0xFFFFu) STEP(cur.w >> 16)
#undef STEP
        }
        ulonglong2 o; o.x = a0; o.y = a1;
        *(ulonglong2*)&g_I[(size_t)row * H_ + h0 + hl * 4] = o;
    }
}

// ---------------- K-tail: hidden LIF -> smem bits -> out GEMM -> out LIF -------
// One block per batch b, 1024 threads.
__global__ __launch_bounds__(1024) void k_tail(const float* __restrict__ hs0,
                                               const float* __restrict__ hv0,
                                               const float* __restrict__ os0,
                                               const float* __restrict__ ov0,
                                               float* __restrict__ out) {
    extern __shared__ float smem_[];
    float*    sWT   = smem_;                          // [H_*DOUT]       80 KB
    float*    sO    = smem_ + H_ * DOUT;              // [256*SOP]       22 KB
    unsigned* sBits = (unsigned*)(sO + 256 * SOP);    // [T_*33]         33 KB
    int b = blockIdx.x, tid = threadIdx.x;

    for (int e = tid; e < H_ * DOUT / 4; e += 1024)
        ((float4*)sWT)[e] = ((const float4*)g_WoT)[e];

    // phase 1: hidden LIF recurrence, spike bits -> smem
    {
        int h = tid, wid = tid >> 5, lane = tid & 31;
        float hv = hv0[b * H_ + h];
        float hs = hs0[b * H_ + h];
        const float* Ip = &g_I[(size_t)(b * T_) * H_ + h];
        for (int t = 0; t < T_; t += 5) {             // 250 % 5 == 0
            float v[5];
#pragma unroll
            for (int k = 0; k < 5; k++) v[k] = Ip[(size_t)(t + k) * H_];
#pragma unroll
            for (int k = 0; k < 5; k++) {
                hv = hv * 0.5f * (1.0f - hs) + v[k];
                bool s = hv > 0.5f;
                hs = s ? 1.0f : 0.0f;
                unsigned m = __ballot_sync(0xffffffffu, s);
                if (lane == 0) sBits[(t + k) * 33 + wid] = m;
            }
        }
    }
    __syncthreads();

    // phase 2: out GEMM via exact ffs walk (ascending h order preserved)
    if (tid < T_) {
        float2 acc[10];
#pragma unroll
        for (int o = 0; o < 10; o++) acc[o] = make_float2(0.0f, 0.0f);
#pragma unroll 4
        for (int w = 0; w < H_ / 32; w++) {
            unsigned word = sBits[tid * 33 + w];
            while (word) {
                int bit = __ffs(word) - 1;
                word &= word - 1;
                const float2* base = (const float2*)&sWT[(w * 32 + bit) * DOUT];
#pragma unroll
                for (int o = 0; o < 10; o++) {
                    float2 v = base[o];
                    acc[o].x += v.x; acc[o].y += v.y;
                }
            }
        }
        float2* od = (float2*)&sO[tid * SOP];
#pragma unroll
        for (int o = 0; o < 10; o++) od[o] = acc[o];
    }
    __syncthreads();

    // phase 3: out LIF recurrence + spike counts
    if (tid < DOUT) {
        float ov = ov0[b * DOUT + tid];
        float os = os0[b * DOUT + tid];
        float cnt = 0.0f;
        for (int tt = 0; tt < T_; tt++) {
            float v = sO[tt * SOP + tid];
            ov = ov * 0.5f * (1.0f - os) + v;
            os = (ov > 0.5f) ? 1.0f : 0.0f;
            cnt += os;
        }
        out[b * DOUT + tid] = cnt;
    }
}

// ---------------- launch ------------------------------------------------------
extern "C" void kernel_launch(void* const* d_in, const int* in_sizes, int n_in,
                              void* d_out, int out_size) {
    const float* sd  = (const float*)d_in[0];   // spike_data [256,700,250]
    const float* Wh  = (const float*)d_in[1];   // W_hid [1024,700]
    const float* Wo  = (const float*)d_in[2];   // W_out [20,1024]
    const float* hs0 = (const float*)d_in[3];   // hid_spike0 [256,1024]
    const float* hv0 = (const float*)d_in[4];   // hid_volt0
    const float* os0 = (const float*)d_in[5];   // out_spike0 [256,20]
    const float* ov0 = (const float*)d_in[6];   // out_volt0
    float* out = (float*)d_out;                 // [256,20] fp32
    (void)in_sizes; (void)n_in; (void)out_size;

    int tail_smem = (H_ * DOUT + 256 * SOP) * 4 + T_ * 33 * 4;   // ~135 KB
    cudaFuncSetAttribute(k_phaseA, cudaFuncAttributeMaxDynamicSharedMemorySize, (DIN + 1) * HS * 4);
    cudaFuncSetAttribute(k_tail,   cudaFuncAttributeMaxDynamicSharedMemorySize, tail_smem);

    k_prep  <<<PACK_BLK + TR_BLK, 256>>>(sd, Wh, Wo);
    k_lists <<<B_ * NW, 256>>>();
    k_phaseA<<<16 * NBG, 1024, (DIN + 1) * HS * 4>>>();
    k_tail  <<<B_, 1024, tail_smem>>>(hs0, hv0, os0, ov0, out);
}